// round 9
// baseline (speedup 1.0000x reference)
#include <cuda_runtime.h>

// Gate on wires {5,13} of a 26-qubit float32 state.
// Flat index bit for wire w is (25 - w): wire5 -> bit 20, wire13 -> bit 12.
// Compact rest index r (24 bits) expands to full address by inserting 0-bits
// at positions 12 and 20. Four amplitudes per group at +0, +2^12, +2^20,
// +2^20+2^12.  out[t] = sum_s U[t*4+s] * x[s], t = b5*2 + b13.
//
// This round: plain loads (streaming hints measured neutral-negative) and
// 8 floats per stream per thread (8 front-batched LDG.128 -> deeper MLP,
// half the threads, half the issue overhead).

#define OFF01 4096u          // 2^12  (wire 13 bit)
#define OFF10 1048576u       // 2^20  (wire 5 bit)

__global__ void __launch_bounds__(256)
unitary_gate_kernel(const float* __restrict__ x,
                    const float* __restrict__ U,
                    float* __restrict__ out) {
    unsigned tid = blockIdx.x * blockDim.x + threadIdx.x;
    unsigned r = tid << 3;  // 8 consecutive rest-indices per thread (bits 0..11 free)

    // expand: r bits [0,11] -> addr [0,11]; [12,18] -> [13,19]; [19,23] -> [21,25]
    unsigned a = (r & 0xFFFu) | ((r & 0x7F000u) << 1) | ((r >> 19) << 21);

    // 8 independent front-batched LDG.128 (MLP_p1 = 8).
    const float4* p00 = reinterpret_cast<const float4*>(x + a);
    const float4* p01 = reinterpret_cast<const float4*>(x + a + OFF01);
    const float4* p10 = reinterpret_cast<const float4*>(x + a + OFF10);
    const float4* p11 = reinterpret_cast<const float4*>(x + a + OFF10 + OFF01);

    const float4 v00a = p00[0], v00b = p00[1];
    const float4 v01a = p01[0], v01b = p01[1];
    const float4 v10a = p10[0], v10b = p10[1];
    const float4 v11a = p11[0], v11b = p11[1];

    const float4 u0 = reinterpret_cast<const float4*>(U)[0];  // row t=0
    const float4 u1 = reinterpret_cast<const float4*>(U)[1];  // row t=1
    const float4 u2 = reinterpret_cast<const float4*>(U)[2];  // row t=2
    const float4 u3 = reinterpret_cast<const float4*>(U)[3];  // row t=3

    float4 o00a, o01a, o10a, o11a, o00b, o01b, o10b, o11b;
#define APPLY(o00,o01,o10,o11,v00,v01,v10,v11,c) \
    o00.c = u0.x * v00.c + u0.y * v01.c + u0.z * v10.c + u0.w * v11.c; \
    o01.c = u1.x * v00.c + u1.y * v01.c + u1.z * v10.c + u1.w * v11.c; \
    o10.c = u2.x * v00.c + u2.y * v01.c + u2.z * v10.c + u2.w * v11.c; \
    o11.c = u3.x * v00.c + u3.y * v01.c + u3.z * v10.c + u3.w * v11.c;

    APPLY(o00a,o01a,o10a,o11a, v00a,v01a,v10a,v11a, x)
    APPLY(o00a,o01a,o10a,o11a, v00a,v01a,v10a,v11a, y)
    APPLY(o00a,o01a,o10a,o11a, v00a,v01a,v10a,v11a, z)
    APPLY(o00a,o01a,o10a,o11a, v00a,v01a,v10a,v11a, w)
    APPLY(o00b,o01b,o10b,o11b, v00b,v01b,v10b,v11b, x)
    APPLY(o00b,o01b,o10b,o11b, v00b,v01b,v10b,v11b, y)
    APPLY(o00b,o01b,o10b,o11b, v00b,v01b,v10b,v11b, z)
    APPLY(o00b,o01b,o10b,o11b, v00b,v01b,v10b,v11b, w)
#undef APPLY

    float4* q00 = reinterpret_cast<float4*>(out + a);
    float4* q01 = reinterpret_cast<float4*>(out + a + OFF01);
    float4* q10 = reinterpret_cast<float4*>(out + a + OFF10);
    float4* q11 = reinterpret_cast<float4*>(out + a + OFF10 + OFF01);

    q00[0] = o00a;  q00[1] = o00b;
    q01[0] = o01a;  q01[1] = o01b;
    q10[0] = o10a;  q10[1] = o10b;
    q11[0] = o11a;  q11[1] = o11b;
}

extern "C" void kernel_launch(void* const* d_in, const int* in_sizes, int n_in,
                              void* d_out, int out_size) {
    const float* x = (const float*)d_in[0];   // 2^26 floats
    const float* U = (const float*)d_in[1];   // 16 floats (4x4 row-major)
    float* out = (float*)d_out;               // 2^26 floats

    // 2^24 rest-groups, 8 per thread -> 2^21 threads
    const int threads = 256;
    const int blocks = (1 << 21) / threads;   // 8192
    unitary_gate_kernel<<<blocks, threads>>>(x, U, out);
}

// round 10
// speedup vs baseline: 1.3140x; 1.3140x over previous
#include <cuda_runtime.h>

// Gate on wires {5,13} of a 26-qubit float32 state.
// Flat index bit for wire w is (25 - w): wire5 -> bit 20, wire13 -> bit 12.
// Compact rest index r (24 bits) expands to full address by inserting 0-bits
// at positions 12 and 20. Four amplitudes per group at +0, +2^12, +2^20,
// +2^20+2^12.  out[t] = sum_s U[t*4+s] * x[s], t = b5*2 + b13.
//
// MLP-8 done RIGHT: each thread keeps the R1 layout (4 consecutive floats,
// warp-dense 128B segments) but processes TWO far-apart rest-groups
// (tid and tid + 2^21). All 8 LDG.128 are front-batched and each is fully
// coalesced within its warp — unlike R7's stride-32B layout which halved
// per-instruction sector efficiency.

#define OFF01 4096u          // 2^12  (wire 13 bit)
#define OFF10 1048576u       // 2^20  (wire 5 bit)

__device__ __forceinline__ unsigned expand(unsigned r) {
    // r bits [0,11] -> addr [0,11]; [12,18] -> [13,19]; [19,23] -> [21,25]
    return (r & 0xFFFu) | ((r & 0x7F000u) << 1) | ((r >> 19) << 21);
}

__global__ void __launch_bounds__(256)
unitary_gate_kernel(const float* __restrict__ x,
                    const float* __restrict__ U,
                    float* __restrict__ out) {
    unsigned tid = blockIdx.x * blockDim.x + threadIdx.x;

    unsigned a0 = expand(tid << 2);                   // group 0
    unsigned a1 = expand((tid + (1u << 21)) << 2);    // group 1 (far half)

    // 8 independent, warp-coalesced, front-batched LDG.128.
    const float4 v00a = *reinterpret_cast<const float4*>(x + a0);
    const float4 v01a = *reinterpret_cast<const float4*>(x + a0 + OFF01);
    const float4 v10a = *reinterpret_cast<const float4*>(x + a0 + OFF10);
    const float4 v11a = *reinterpret_cast<const float4*>(x + a0 + OFF10 + OFF01);
    const float4 v00b = *reinterpret_cast<const float4*>(x + a1);
    const float4 v01b = *reinterpret_cast<const float4*>(x + a1 + OFF01);
    const float4 v10b = *reinterpret_cast<const float4*>(x + a1 + OFF10);
    const float4 v11b = *reinterpret_cast<const float4*>(x + a1 + OFF10 + OFF01);

    const float4 u0 = reinterpret_cast<const float4*>(U)[0];  // row t=0
    const float4 u1 = reinterpret_cast<const float4*>(U)[1];  // row t=1
    const float4 u2 = reinterpret_cast<const float4*>(U)[2];  // row t=2
    const float4 u3 = reinterpret_cast<const float4*>(U)[3];  // row t=3

    float4 o00a, o01a, o10a, o11a, o00b, o01b, o10b, o11b;
#define APPLY(o00,o01,o10,o11,v00,v01,v10,v11,c) \
    o00.c = u0.x * v00.c + u0.y * v01.c + u0.z * v10.c + u0.w * v11.c; \
    o01.c = u1.x * v00.c + u1.y * v01.c + u1.z * v10.c + u1.w * v11.c; \
    o10.c = u2.x * v00.c + u2.y * v01.c + u2.z * v10.c + u2.w * v11.c; \
    o11.c = u3.x * v00.c + u3.y * v01.c + u3.z * v10.c + u3.w * v11.c;

    APPLY(o00a,o01a,o10a,o11a, v00a,v01a,v10a,v11a, x)
    APPLY(o00a,o01a,o10a,o11a, v00a,v01a,v10a,v11a, y)
    APPLY(o00a,o01a,o10a,o11a, v00a,v01a,v10a,v11a, z)
    APPLY(o00a,o01a,o10a,o11a, v00a,v01a,v10a,v11a, w)
    APPLY(o00b,o01b,o10b,o11b, v00b,v01b,v10b,v11b, x)
    APPLY(o00b,o01b,o10b,o11b, v00b,v01b,v10b,v11b, y)
    APPLY(o00b,o01b,o10b,o11b, v00b,v01b,v10b,v11b, z)
    APPLY(o00b,o01b,o10b,o11b, v00b,v01b,v10b,v11b, w)
#undef APPLY

    *reinterpret_cast<float4*>(out + a0)                 = o00a;
    *reinterpret_cast<float4*>(out + a0 + OFF01)         = o01a;
    *reinterpret_cast<float4*>(out + a0 + OFF10)         = o10a;
    *reinterpret_cast<float4*>(out + a0 + OFF10 + OFF01) = o11a;
    *reinterpret_cast<float4*>(out + a1)                 = o00b;
    *reinterpret_cast<float4*>(out + a1 + OFF01)         = o01b;
    *reinterpret_cast<float4*>(out + a1 + OFF10)         = o10b;
    *reinterpret_cast<float4*>(out + a1 + OFF10 + OFF01) = o11b;
}

extern "C" void kernel_launch(void* const* d_in, const int* in_sizes, int n_in,
                              void* d_out, int out_size) {
    const float* x = (const float*)d_in[0];   // 2^26 floats
    const float* U = (const float*)d_in[1];   // 16 floats (4x4 row-major)
    float* out = (float*)d_out;               // 2^26 floats

    // 2^24 rest-groups, 2 groups x 4 floats per thread -> 2^21 threads
    const int threads = 256;
    const int blocks = (1 << 21) / threads;   // 8192
    unitary_gate_kernel<<<blocks, threads>>>(x, U, out);
}

// round 12
// speedup vs baseline: 1.3247x; 1.0082x over previous
#include <cuda_runtime.h>

// Gate on wires {5,13} of a 26-qubit float32 state.
// Flat index bit for wire w is (25 - w): wire5 -> bit 20, wire13 -> bit 12.
// Compact rest index r (24 bits) expands to full address by inserting 0-bits
// at positions 12 and 20. Four amplitudes per group at +0, +2^12, +2^20,
// +2^20+2^12.  out[t] = sum_s U[t*4+s] * x[s], t = b5*2 + b13.
//
// This round: 256-bit global accesses (sm_10x LDG.E.256 / STG.E.256).
// Each thread owns 8 CONSECUTIVE floats per stream (32B, 32B-aligned since
// OFF01/OFF10 are multiples of 4096 floats). One v8 load per stream is fully
// sector-dense per instruction (unlike R7's paired LDG.128 at 32B stride),
// and halves LSU/L1tex wavefront instruction count per byte.

#define OFF01 4096u          // 2^12  (wire 13 bit)
#define OFF10 1048576u       // 2^20  (wire 5 bit)

struct f8 { float a0, a1, a2, a3, a4, a5, a6, a7; };

__device__ __forceinline__ f8 ldg256(const float* p) {
    f8 r;
    asm("ld.global.v8.f32 {%0,%1,%2,%3,%4,%5,%6,%7}, [%8];"
        : "=f"(r.a0), "=f"(r.a1), "=f"(r.a2), "=f"(r.a3),
          "=f"(r.a4), "=f"(r.a5), "=f"(r.a6), "=f"(r.a7)
        : "l"(p));
    return r;
}

__device__ __forceinline__ void stg256(float* p, const f8& r) {
    asm volatile("st.global.v8.f32 [%8], {%0,%1,%2,%3,%4,%5,%6,%7};"
        :: "f"(r.a0), "f"(r.a1), "f"(r.a2), "f"(r.a3),
           "f"(r.a4), "f"(r.a5), "f"(r.a6), "f"(r.a7),
           "l"(p)
        : "memory");
}

__global__ void __launch_bounds__(256)
unitary_gate_kernel(const float* __restrict__ x,
                    const float* __restrict__ U,
                    float* __restrict__ out) {
    unsigned tid = blockIdx.x * blockDim.x + threadIdx.x;
    unsigned r = tid << 3;  // 8 consecutive rest-indices per thread (bits 0..11 free)

    // expand: r bits [0,11] -> addr [0,11]; [12,18] -> [13,19]; [19,23] -> [21,25]
    unsigned a = (r & 0xFFFu) | ((r & 0x7F000u) << 1) | ((r >> 19) << 21);

    // 4 front-batched 256-bit loads, each fully warp-dense (1KB/warp/instr).
    f8 v00 = ldg256(x + a);
    f8 v01 = ldg256(x + a + OFF01);
    f8 v10 = ldg256(x + a + OFF10);
    f8 v11 = ldg256(x + a + OFF10 + OFF01);

    const float4 u0 = reinterpret_cast<const float4*>(U)[0];  // row t=0
    const float4 u1 = reinterpret_cast<const float4*>(U)[1];  // row t=1
    const float4 u2 = reinterpret_cast<const float4*>(U)[2];  // row t=2
    const float4 u3 = reinterpret_cast<const float4*>(U)[3];  // row t=3

    f8 o00, o01, o10, o11;
#define APPLY(c) \
    o00.c = u0.x * v00.c + u0.y * v01.c + u0.z * v10.c + u0.w * v11.c; \
    o01.c = u1.x * v00.c + u1.y * v01.c + u1.z * v10.c + u1.w * v11.c; \
    o10.c = u2.x * v00.c + u2.y * v01.c + u2.z * v10.c + u2.w * v11.c; \
    o11.c = u3.x * v00.c + u3.y * v01.c + u3.z * v10.c + u3.w * v11.c;
    APPLY(a0) APPLY(a1) APPLY(a2) APPLY(a3)
    APPLY(a4) APPLY(a5) APPLY(a6) APPLY(a7)
#undef APPLY

    stg256(out + a,                 o00);
    stg256(out + a + OFF01,         o01);
    stg256(out + a + OFF10,         o10);
    stg256(out + a + OFF10 + OFF01, o11);
}

extern "C" void kernel_launch(void* const* d_in, const int* in_sizes, int n_in,
                              void* d_out, int out_size) {
    const float* x = (const float*)d_in[0];   // 2^26 floats
    const float* U = (const float*)d_in[1];   // 16 floats (4x4 row-major)
    float* out = (float*)d_out;               // 2^26 floats

    // 2^24 rest-groups, 8 floats per stream per thread -> 2^21 threads
    const int threads = 256;
    const int blocks = (1 << 21) / threads;   // 8192
    unitary_gate_kernel<<<blocks, threads>>>(x, U, out);
}